// round 1
// baseline (speedup 1.0000x reference)
#include <cuda_runtime.h>
#include <math.h>

#define B_  2
#define T_  2048
#define D_  1024
#define H_  16
#define DH  64

// Scratch (allocation-free contract: __device__ globals)
__device__ float g_Q[B_*H_*T_*DH];
__device__ float g_K[B_*H_*T_*DH];
__device__ float g_V[B_*H_*T_*DH];
__device__ float g_attn[(size_t)B_*T_*D_];

// ---------------------------------------------------------------------------
// C = A (MxK, row-major) @ W^T  (W: NxK, row-major)
// outmode 0: C row-major [M,N]
// outmode 1: scatter to per-head layout [(b*H+h)][t][d]  (n = h*64+d, m = b*T+t)
// ---------------------------------------------------------------------------
__global__ __launch_bounds__(256) void sgemm_nt(
    const float* __restrict__ A, const float* __restrict__ W,
    float* __restrict__ C, int M, int N, int K, int outmode)
{
    __shared__ __align__(16) float As[16][68];
    __shared__ __align__(16) float Bs[16][68];
    const int tid = threadIdx.x;
    const int bm = blockIdx.y << 6;
    const int bn = blockIdx.x << 6;
    const int ty = tid >> 4, tx = tid & 15;
    const int lrow = tid >> 2;
    const int lk   = (tid & 3) << 2;

    float acc[4][4];
#pragma unroll
    for (int i = 0; i < 4; i++)
#pragma unroll
        for (int j = 0; j < 4; j++) acc[i][j] = 0.f;

    const float* Aptr = A + (size_t)(bm + lrow) * K + lk;
    const float* Wptr = W + (size_t)(bn + lrow) * K + lk;

    for (int k0 = 0; k0 < K; k0 += 16) {
        float4 av = *(const float4*)(Aptr + k0);
        float4 bv = *(const float4*)(Wptr + k0);
        __syncthreads();
        As[lk+0][lrow] = av.x; As[lk+1][lrow] = av.y;
        As[lk+2][lrow] = av.z; As[lk+3][lrow] = av.w;
        Bs[lk+0][lrow] = bv.x; Bs[lk+1][lrow] = bv.y;
        Bs[lk+2][lrow] = bv.z; Bs[lk+3][lrow] = bv.w;
        __syncthreads();
#pragma unroll
        for (int kk = 0; kk < 16; kk++) {
            float4 a = *(const float4*)&As[kk][ty << 2];
            float4 b = *(const float4*)&Bs[kk][tx << 2];
            acc[0][0] += a.x*b.x; acc[0][1] += a.x*b.y; acc[0][2] += a.x*b.z; acc[0][3] += a.x*b.w;
            acc[1][0] += a.y*b.x; acc[1][1] += a.y*b.y; acc[1][2] += a.y*b.z; acc[1][3] += a.y*b.w;
            acc[2][0] += a.z*b.x; acc[2][1] += a.z*b.y; acc[2][2] += a.z*b.z; acc[2][3] += a.z*b.w;
            acc[3][0] += a.w*b.x; acc[3][1] += a.w*b.y; acc[3][2] += a.w*b.z; acc[3][3] += a.w*b.w;
        }
    }

    const int n0 = bn + (tx << 2);
    if (outmode == 0) {
#pragma unroll
        for (int i = 0; i < 4; i++) {
            int row = bm + (ty << 2) + i;
            float4 o = make_float4(acc[i][0], acc[i][1], acc[i][2], acc[i][3]);
            *(float4*)(C + (size_t)row * N + n0) = o;
        }
    } else {
        int h = n0 >> 6, d = n0 & 63;
#pragma unroll
        for (int i = 0; i < 4; i++) {
            int row = bm + (ty << 2) + i;
            int b = row >> 11, t = row & 2047;
            float4 o = make_float4(acc[i][0], acc[i][1], acc[i][2], acc[i][3]);
            *(float4*)(C + (((size_t)(b * H_ + h) * T_ + t) * DH + d)) = o;
        }
    }
}

// ---------------------------------------------------------------------------
// Flash attention, fp32, one query row per thread (128 rows / block).
// Q,K,V: [B*H][T][64]; O: [B][T][D] (scattered to h*64+d).
// ---------------------------------------------------------------------------
__global__ __launch_bounds__(128) void flash_attn(
    const float* __restrict__ Q, const float* __restrict__ K,
    const float* __restrict__ V, const unsigned char* __restrict__ mask,
    float* __restrict__ O)
{
    __shared__ __align__(16) float Ks[64][64];
    __shared__ __align__(16) float Vs[64][64];

    const int bh = blockIdx.y;
    const int b  = bh >> 4;
    const int h  = bh & 15;
    const int r  = blockIdx.x * 128 + threadIdx.x;

    const float* qrow = Q + ((size_t)bh * T_ + r) * DH;
    float4 q4[16];
#pragma unroll
    for (int i = 0; i < 16; i++) {
        float4 t = ((const float4*)qrow)[i];
        t.x *= 0.125f; t.y *= 0.125f; t.z *= 0.125f; t.w *= 0.125f;  // 1/sqrt(64)
        q4[i] = t;
    }
    float4 acc4[16];
#pragma unroll
    for (int i = 0; i < 16; i++) acc4[i] = make_float4(0.f, 0.f, 0.f, 0.f);

    float mmax = -1e30f, l = 0.f;
    const unsigned char* mrow = mask + ((size_t)b * T_ + r) * (size_t)T_;

    for (int kt = 0; kt < T_; kt += 64) {
        const float4* Kg = (const float4*)(K + ((size_t)bh * T_ + kt) * DH);
        const float4* Vg = (const float4*)(V + ((size_t)bh * T_ + kt) * DH);
        __syncthreads();
#pragma unroll
        for (int i = threadIdx.x; i < 1024; i += 128) {
            ((float4*)Ks)[i] = Kg[i];
            ((float4*)Vs)[i] = Vg[i];
        }
        __syncthreads();

#pragma unroll 1
        for (int j0 = 0; j0 < 64; j0 += 16) {
            float s[16];
#pragma unroll
            for (int j = 0; j < 16; j++) {
                const float4* krow = (const float4*)Ks[j0 + j];
                float s0 = 0.f, s1 = 0.f, s2 = 0.f, s3 = 0.f;
#pragma unroll
                for (int d4 = 0; d4 < 16; d4++) {
                    float4 kk = krow[d4];
                    s0 += q4[d4].x * kk.x;
                    s1 += q4[d4].y * kk.y;
                    s2 += q4[d4].z * kk.z;
                    s3 += q4[d4].w * kk.w;
                }
                s[j] = (s0 + s1) + (s2 + s3);
            }
            // mask (bool bytes; all-zero in this dataset but handled generically)
            const unsigned char* mk = mrow + kt + j0;
#pragma unroll
            for (int j = 0; j < 16; j++) if (mk[j]) s[j] = -1e30f;

            float chm = s[0];
#pragma unroll
            for (int j = 1; j < 16; j++) chm = fmaxf(chm, s[j]);
            float mnew = fmaxf(mmax, chm);
            float corr = __expf(mmax - mnew);
            float p[16];
            float ls = 0.f;
#pragma unroll
            for (int j = 0; j < 16; j++) { p[j] = __expf(s[j] - mnew); ls += p[j]; }
            l = l * corr + ls;
            mmax = mnew;
#pragma unroll
            for (int d4 = 0; d4 < 16; d4++) {
                float4 a = acc4[d4];
                a.x *= corr; a.y *= corr; a.z *= corr; a.w *= corr;
#pragma unroll
                for (int j = 0; j < 16; j++) {
                    float4 vv = ((const float4*)Vs[j0 + j])[d4];
                    a.x += p[j] * vv.x;
                    a.y += p[j] * vv.y;
                    a.z += p[j] * vv.z;
                    a.w += p[j] * vv.w;
                }
                acc4[d4] = a;
            }
        }
    }

    float inv = 1.f / l;
    float* orow = O + ((size_t)b * T_ + r) * D_ + h * DH;
#pragma unroll
    for (int i = 0; i < 16; i++) {
        float4 a = acc4[i];
        a.x *= inv; a.y *= inv; a.z *= inv; a.w *= inv;
        ((float4*)orow)[i] = a;
    }
}

extern "C" void kernel_launch(void* const* d_in, const int* in_sizes, int n_in,
                              void* d_out, int out_size)
{
    const float* query = (const float*)d_in[0];
    const float* key   = (const float*)d_in[1];
    const float* value = (const float*)d_in[2];
    const unsigned char* mask = (const unsigned char*)d_in[3];
    const float* Wq = (const float*)d_in[4];
    const float* Wk = (const float*)d_in[5];
    const float* Wv = (const float*)d_in[6];
    const float* Wo = (const float*)d_in[7];

    void *pQ, *pK, *pV, *pA;
    cudaGetSymbolAddress(&pQ, g_Q);
    cudaGetSymbolAddress(&pK, g_K);
    cudaGetSymbolAddress(&pV, g_V);
    cudaGetSymbolAddress(&pA, g_attn);

    const int M = B_ * T_;   // 4096
    const int N = D_;        // 1024
    const int K = D_;        // 1024

    dim3 gg(N / 64, M / 64);          // (16, 64)
    sgemm_nt<<<gg, 256>>>(query, Wq, (float*)pQ, M, N, K, 1);
    sgemm_nt<<<gg, 256>>>(key,   Wk, (float*)pK, M, N, K, 1);
    sgemm_nt<<<gg, 256>>>(value, Wv, (float*)pV, M, N, K, 1);

    dim3 ga(T_ / 128, B_ * H_);       // (16, 32)
    flash_attn<<<ga, 128>>>((const float*)pQ, (const float*)pK, (const float*)pV,
                            mask, (float*)pA);

    sgemm_nt<<<gg, 256>>>((const float*)pA, Wo, (float*)d_out, M, N, K, 0);
}

// round 3
// speedup vs baseline: 1.0356x; 1.0356x over previous
#include <cuda_runtime.h>
#include <cstdint>
#include <math.h>

#define B_  2
#define T_  2048
#define D_  1024
#define H_  16
#define DH  64

// Scratch (allocation-free contract: __device__ globals)
__device__ float g_Q[B_*H_*T_*DH];
__device__ float g_K[B_*H_*T_*DH];
__device__ float g_V[B_*H_*T_*DH];
__device__ float g_attn[(size_t)B_*T_*D_];

// ---------------------------------------------------------------------------
// tf32 helpers (base-target PTX only; no tcgen05 — unsupported by this harness)
// ---------------------------------------------------------------------------
__device__ __forceinline__ void split_tf32(float a, uint32_t& h, uint32_t& l) {
    uint32_t hb; asm("cvt.rna.tf32.f32 %0, %1;" : "=r"(hb) : "f"(a));
    float r = a - __uint_as_float(hb);
    uint32_t lb; asm("cvt.rna.tf32.f32 %0, %1;" : "=r"(lb) : "f"(r));
    h = hb; l = lb;
}

__device__ __forceinline__ void mma_tf32(float* d,
    uint32_t a0, uint32_t a1, uint32_t a2, uint32_t a3,
    uint32_t b0, uint32_t b1)
{
    asm volatile(
        "mma.sync.aligned.m16n8k8.row.col.f32.tf32.tf32.f32 "
        "{%0,%1,%2,%3}, {%4,%5,%6,%7}, {%8,%9}, {%0,%1,%2,%3};"
        : "+f"(d[0]), "+f"(d[1]), "+f"(d[2]), "+f"(d[3])
        : "r"(a0), "r"(a1), "r"(a2), "r"(a3), "r"(b0), "r"(b1));
}

// ---------------------------------------------------------------------------
// C = A (MxK row-major) @ W^T (W: NxK row-major), M=4096, N=K=1024.
// Tile 128x128, K_tile=32, 8 warps, warp tile 64x32, m16n8k8 tf32 hi/lo split.
// Smem: (hi,lo) uint2 at word offset row*72 + k*2 (row stride 72 words).
// outmode 0: C row-major [M,1024]; outmode 1: per-head scatter.
// ---------------------------------------------------------------------------
#define STRIDE_R 72
__global__ __launch_bounds__(256) void tf32_gemm(
    const float* __restrict__ A, const float* __restrict__ W,
    float* __restrict__ C, int outmode)
{
    extern __shared__ __align__(16) char smem[];
    uint32_t* Sa = (uint32_t*)smem;                       // 128 * 72 words
    uint32_t* Sb = (uint32_t*)(smem + 128 * STRIDE_R * 4);

    const int tid  = threadIdx.x;
    const int bm   = blockIdx.y * 128;
    const int bn   = blockIdx.x * 128;
    const int wid  = tid >> 5, lane = tid & 31;
    const int wm   = (wid & 1) * 64;     // 2 warps along M
    const int wn   = (wid >> 1) * 32;    // 4 warps along N

    float acc[4][4][4];
#pragma unroll
    for (int mt = 0; mt < 4; mt++)
#pragma unroll
        for (int nt = 0; nt < 4; nt++)
#pragma unroll
            for (int i = 0; i < 4; i++) acc[mt][nt][i] = 0.f;

    const int lr = tid >> 3;   // 0..31
    const int c4 = tid & 7;    // 0..7

    for (int it = 0; it < 32; ++it) {
        const int kt = it * 32;
        float aR[4][4], bR[4][4];
#pragma unroll
        for (int p = 0; p < 4; ++p) {
            const float* Ap = A + (size_t)(bm + p * 32 + lr) * 1024 + kt + c4;
            const float* Wp = W + (size_t)(bn + p * 32 + lr) * 1024 + kt + c4;
#pragma unroll
            for (int j = 0; j < 4; ++j) { aR[p][j] = Ap[8 * j]; bR[p][j] = Wp[8 * j]; }
        }
        __syncthreads();   // previous iter's fragment reads done
#pragma unroll
        for (int p = 0; p < 4; ++p) {
            const int row = p * 32 + lr;
#pragma unroll
            for (int j = 0; j < 4; ++j) {
                const int k = c4 + 8 * j;
                uint32_t h, l;
                split_tf32(aR[p][j], h, l);
                *(uint2*)&Sa[row * STRIDE_R + k * 2] = make_uint2(h, l);
                split_tf32(bR[p][j], h, l);
                *(uint2*)&Sb[row * STRIDE_R + k * 2] = make_uint2(h, l);
            }
        }
        __syncthreads();

#pragma unroll
        for (int c = 0; c < 4; ++c) {
            uint2 aF[4][4];
#pragma unroll
            for (int mt = 0; mt < 4; ++mt) {
                const int r0 = wm + mt * 16 + (lane >> 2);
                const int kk = c * 8 + (lane & 3);
                aF[mt][0] = *(const uint2*)&Sa[r0 * STRIDE_R + kk * 2];
                aF[mt][1] = *(const uint2*)&Sa[(r0 + 8) * STRIDE_R + kk * 2];
                aF[mt][2] = *(const uint2*)&Sa[r0 * STRIDE_R + (kk + 4) * 2];
                aF[mt][3] = *(const uint2*)&Sa[(r0 + 8) * STRIDE_R + (kk + 4) * 2];
            }
            uint2 bF[4][2];
#pragma unroll
            for (int nt = 0; nt < 4; ++nt) {
                const int cc = wn + nt * 8 + (lane >> 2);
                const int kk = c * 8 + (lane & 3);
                bF[nt][0] = *(const uint2*)&Sb[cc * STRIDE_R + kk * 2];
                bF[nt][1] = *(const uint2*)&Sb[cc * STRIDE_R + (kk + 4) * 2];
            }
#pragma unroll
            for (int mt = 0; mt < 4; ++mt)
#pragma unroll
                for (int nt = 0; nt < 4; ++nt) {
                    float* d = acc[mt][nt];
                    // hi*hi
                    mma_tf32(d, aF[mt][0].x, aF[mt][1].x, aF[mt][2].x, aF[mt][3].x,
                             bF[nt][0].x, bF[nt][1].x);
                    // hi*lo
                    mma_tf32(d, aF[mt][0].x, aF[mt][1].x, aF[mt][2].x, aF[mt][3].x,
                             bF[nt][0].y, bF[nt][1].y);
                    // lo*hi
                    mma_tf32(d, aF[mt][0].y, aF[mt][1].y, aF[mt][2].y, aF[mt][3].y,
                             bF[nt][0].x, bF[nt][1].x);
                }
        }
    }

    // Epilogue: c0/c1 at (row, col0), c2/c3 at (row+8, col0)
#pragma unroll
    for (int mt = 0; mt < 4; ++mt) {
#pragma unroll
        for (int nt = 0; nt < 4; ++nt) {
            const int row  = bm + wm + mt * 16 + (lane >> 2);
            const int col0 = bn + wn + nt * 8 + (lane & 3) * 2;
            const float* d = acc[mt][nt];
            if (outmode == 0) {
                *(float2*)(C + (size_t)row * 1024 + col0)       = make_float2(d[0], d[1]);
                *(float2*)(C + (size_t)(row + 8) * 1024 + col0) = make_float2(d[2], d[3]);
            } else {
                const int h = col0 >> 6, dd = col0 & 63;
                int b = row >> 11, t = row & 2047;
                *(float2*)(C + (((size_t)(b * H_ + h) * T_ + t) * DH + dd)) = make_float2(d[0], d[1]);
                b = (row + 8) >> 11; t = (row + 8) & 2047;
                *(float2*)(C + (((size_t)(b * H_ + h) * T_ + t) * DH + dd)) = make_float2(d[2], d[3]);
            }
        }
    }
}

// ---------------------------------------------------------------------------
// Flash attention, fp32, one query row per thread (unchanged; near fp32 roofline)
// ---------------------------------------------------------------------------
__global__ __launch_bounds__(128) void flash_attn(
    const float* __restrict__ Q, const float* __restrict__ K,
    const float* __restrict__ V, const unsigned char* __restrict__ mask,
    float* __restrict__ O)
{
    __shared__ __align__(16) float Ks[64][64];
    __shared__ __align__(16) float Vs[64][64];

    const int bh = blockIdx.y;
    const int b  = bh >> 4;
    const int h  = bh & 15;
    const int r  = blockIdx.x * 128 + threadIdx.x;

    const float* qrow = Q + ((size_t)bh * T_ + r) * DH;
    float4 q4[16];
#pragma unroll
    for (int i = 0; i < 16; i++) {
        float4 t = ((const float4*)qrow)[i];
        t.x *= 0.125f; t.y *= 0.125f; t.z *= 0.125f; t.w *= 0.125f;
        q4[i] = t;
    }
    float4 acc4[16];
#pragma unroll
    for (int i = 0; i < 16; i++) acc4[i] = make_float4(0.f, 0.f, 0.f, 0.f);

    float mmax = -1e30f, l = 0.f;
    const unsigned char* mrow = mask + ((size_t)b * T_ + r) * (size_t)T_;

    for (int kt = 0; kt < T_; kt += 64) {
        const float4* Kg = (const float4*)(K + ((size_t)bh * T_ + kt) * DH);
        const float4* Vg = (const float4*)(V + ((size_t)bh * T_ + kt) * DH);
        __syncthreads();
#pragma unroll
        for (int i = threadIdx.x; i < 1024; i += 128) {
            ((float4*)Ks)[i] = Kg[i];
            ((float4*)Vs)[i] = Vg[i];
        }
        __syncthreads();

#pragma unroll 1
        for (int j0 = 0; j0 < 64; j0 += 16) {
            float s[16];
#pragma unroll
            for (int j = 0; j < 16; j++) {
                const float4* krow = (const float4*)Ks[j0 + j];
                float s0 = 0.f, s1 = 0.f, s2 = 0.f, s3 = 0.f;
#pragma unroll
                for (int d4 = 0; d4 < 16; d4++) {
                    float4 kk = krow[d4];
                    s0 += q4[d4].x * kk.x;
                    s1 += q4[d4].y * kk.y;
                    s2 += q4[d4].z * kk.z;
                    s3 += q4[d4].w * kk.w;
                }
                s[j] = (s0 + s1) + (s2 + s3);
            }
            const unsigned char* mk = mrow + kt + j0;
#pragma unroll
            for (int j = 0; j < 16; j++) if (mk[j]) s[j] = -1e30f;

            float chm = s[0];
#pragma unroll
            for (int j = 1; j < 16; j++) chm = fmaxf(chm, s[j]);
            float mnew = fmaxf(mmax, chm);
            float corr = __expf(mmax - mnew);
            float p[16];
            float ls = 0.f;
#pragma unroll
            for (int j = 0; j < 16; j++) { p[j] = __expf(s[j] - mnew); ls += p[j]; }
            l = l * corr + ls;
            mmax = mnew;
#pragma unroll
            for (int d4 = 0; d4 < 16; d4++) {
                float4 a = acc4[d4];
                a.x *= corr; a.y *= corr; a.z *= corr; a.w *= corr;
#pragma unroll
                for (int j = 0; j < 16; j++) {
                    float4 vv = ((const float4*)Vs[j0 + j])[d4];
                    a.x += p[j] * vv.x;
                    a.y += p[j] * vv.y;
                    a.z += p[j] * vv.z;
                    a.w += p[j] * vv.w;
                }
                acc4[d4] = a;
            }
        }
    }

    float inv = 1.f / l;
    float* orow = O + ((size_t)b * T_ + r) * D_ + h * DH;
#pragma unroll
    for (int i = 0; i < 16; i++) {
        float4 a = acc4[i];
        a.x *= inv; a.y *= inv; a.z *= inv; a.w *= inv;
        ((float4*)orow)[i] = a;
    }
}

extern "C" void kernel_launch(void* const* d_in, const int* in_sizes, int n_in,
                              void* d_out, int out_size)
{
    const float* query = (const float*)d_in[0];
    const float* key   = (const float*)d_in[1];
    const float* value = (const float*)d_in[2];
    const unsigned char* mask = (const unsigned char*)d_in[3];
    const float* Wq = (const float*)d_in[4];
    const float* Wk = (const float*)d_in[5];
    const float* Wv = (const float*)d_in[6];
    const float* Wo = (const float*)d_in[7];

    void *pQ, *pK, *pV, *pA;
    cudaGetSymbolAddress(&pQ, g_Q);
    cudaGetSymbolAddress(&pK, g_K);
    cudaGetSymbolAddress(&pV, g_V);
    cudaGetSymbolAddress(&pA, g_attn);

    const int SMEM_TOTAL = 2 * 128 * STRIDE_R * 4;   // 73728 B
    static bool attr_set = false;
    if (!attr_set) {
        cudaFuncSetAttribute(tf32_gemm, cudaFuncAttributeMaxDynamicSharedMemorySize, SMEM_TOTAL);
        attr_set = true;
    }

    dim3 gg(1024 / 128, 4096 / 128);   // (8, 32)
    tf32_gemm<<<gg, 256, SMEM_TOTAL>>>(query, Wq, (float*)pQ, 1);
    tf32_gemm<<<gg, 256, SMEM_TOTAL>>>(key,   Wk, (float*)pK, 1);
    tf32_gemm<<<gg, 256, SMEM_TOTAL>>>(value, Wv, (float*)pV, 1);

    dim3 ga(T_ / 128, B_ * H_);        // (16, 32)
    flash_attn<<<ga, 128>>>((const float*)pQ, (const float*)pK, (const float*)pV,
                            mask, (float*)pA);

    tf32_gemm<<<gg, 256, SMEM_TOTAL>>>((const float*)pA, Wo, (float*)d_out, 0);
}

// round 4
// speedup vs baseline: 2.9547x; 2.8532x over previous
#include <cuda_runtime.h>
#include <cstdint>
#include <math.h>

#define B_  2
#define T_  2048
#define D_  1024
#define H_  16
#define DH  64

// Scratch (allocation-free contract: __device__ globals)
__device__ float g_Q[B_*H_*T_*DH];
__device__ float g_K[B_*H_*T_*DH];
__device__ float g_V[B_*H_*T_*DH];
__device__ float g_attn[(size_t)B_*T_*D_];

// ---------------------------------------------------------------------------
// bf16 split helpers: x = hi + lo captures ~17 mantissa bits.
// packbf: x -> low 16 bits, y -> high 16 bits (mma element order: low = even k)
// ---------------------------------------------------------------------------
__device__ __forceinline__ uint32_t packbf(float x, float y) {
    uint32_t r; asm("cvt.rn.bf16x2.f32 %0, %1, %2;" : "=r"(r) : "f"(y), "f"(x)); return r;
}
__device__ __forceinline__ void split2(float x, float y, uint32_t& h, uint32_t& l) {
    h = packbf(x, y);
    float hx = __uint_as_float(h << 16);
    float hy = __uint_as_float(h & 0xFFFF0000u);
    l = packbf(x - hx, y - hy);
}
__device__ __forceinline__ void mma_bf16(float* d, const uint32_t* a, uint32_t b0, uint32_t b1) {
    asm volatile("mma.sync.aligned.m16n8k16.row.col.f32.bf16.bf16.f32 "
        "{%0,%1,%2,%3}, {%4,%5,%6,%7}, {%8,%9}, {%0,%1,%2,%3};"
        : "+f"(d[0]), "+f"(d[1]), "+f"(d[2]), "+f"(d[3])
        : "r"(a[0]), "r"(a[1]), "r"(a[2]), "r"(a[3]), "r"(b0), "r"(b1));
}

// ---------------------------------------------------------------------------
// C = A (MxK row-major) @ W^T (W: NxK row-major), M=4096, N=K=1024.
// 128x128 tile, K_tile=32, 8 warps (warp tile 64x32), m16n8k16 bf16 3-term split.
// Smem: packed bf16x2 words [row][khalf], stride 20 words (conflict-free frags).
// ---------------------------------------------------------------------------
#define GSTR 20
__global__ __launch_bounds__(256) void bf16_gemm(
    const float* __restrict__ A, const float* __restrict__ W,
    float* __restrict__ C, int outmode)
{
    __shared__ uint32_t Sah[128*GSTR], Sal[128*GSTR], Sbh[128*GSTR], Sbl[128*GSTR];

    const int tid  = threadIdx.x;
    const int bm   = blockIdx.y * 128;
    const int bn   = blockIdx.x * 128;
    const int wid  = tid >> 5, lane = tid & 31;
    const int wm   = (wid & 1) * 64;
    const int wn   = (wid >> 1) * 32;
    const int lr   = lane >> 2, lc = lane & 3;

    float acc[4][4][4];
#pragma unroll
    for (int mt = 0; mt < 4; mt++)
#pragma unroll
        for (int nt = 0; nt < 4; nt++)
#pragma unroll
            for (int i = 0; i < 4; i++) acc[mt][nt][i] = 0.f;

    const int kh   = tid & 15;      // khalf 0..15 (32 k values)
    const int row0 = tid >> 4;      // 0..15

    for (int it = 0; it < 32; ++it) {
        const int kt = it * 32;
        float2 aR[8], bR[8];
#pragma unroll
        for (int p = 0; p < 8; ++p) {
            int row = row0 + p * 16;
            aR[p] = *(const float2*)(A + (size_t)(bm + row) * 1024 + kt + 2 * kh);
            bR[p] = *(const float2*)(W + (size_t)(bn + row) * 1024 + kt + 2 * kh);
        }
        __syncthreads();
#pragma unroll
        for (int p = 0; p < 8; ++p) {
            int row = row0 + p * 16;
            uint32_t h, l;
            split2(aR[p].x, aR[p].y, h, l);
            Sah[row * GSTR + kh] = h; Sal[row * GSTR + kh] = l;
            split2(bR[p].x, bR[p].y, h, l);
            Sbh[row * GSTR + kh] = h; Sbl[row * GSTR + kh] = l;
        }
        __syncthreads();

#pragma unroll
        for (int c = 0; c < 2; ++c) {
            uint32_t ah[4][4], al[4][4];
#pragma unroll
            for (int mt = 0; mt < 4; ++mt) {
                const int r0 = wm + mt * 16 + lr;
                const int k0 = c * 8 + lc;
                ah[mt][0] = Sah[r0 * GSTR + k0];
                ah[mt][1] = Sah[(r0 + 8) * GSTR + k0];
                ah[mt][2] = Sah[r0 * GSTR + k0 + 4];
                ah[mt][3] = Sah[(r0 + 8) * GSTR + k0 + 4];
                al[mt][0] = Sal[r0 * GSTR + k0];
                al[mt][1] = Sal[(r0 + 8) * GSTR + k0];
                al[mt][2] = Sal[r0 * GSTR + k0 + 4];
                al[mt][3] = Sal[(r0 + 8) * GSTR + k0 + 4];
            }
#pragma unroll
            for (int nt = 0; nt < 4; ++nt) {
                const int cc = wn + nt * 8 + lr;
                const int k0 = c * 8 + lc;
                uint32_t bh0 = Sbh[cc * GSTR + k0];
                uint32_t bh1 = Sbh[cc * GSTR + k0 + 4];
                uint32_t bl0 = Sbl[cc * GSTR + k0];
                uint32_t bl1 = Sbl[cc * GSTR + k0 + 4];
#pragma unroll
                for (int mt = 0; mt < 4; ++mt) {
                    mma_bf16(acc[mt][nt], ah[mt], bh0, bh1);
                    mma_bf16(acc[mt][nt], ah[mt], bl0, bl1);
                    mma_bf16(acc[mt][nt], al[mt], bh0, bh1);
                }
            }
        }
    }

#pragma unroll
    for (int mt = 0; mt < 4; ++mt) {
#pragma unroll
        for (int nt = 0; nt < 4; ++nt) {
            const int row  = bm + wm + mt * 16 + lr;
            const int col0 = bn + wn + nt * 8 + lc * 2;
            const float* d = acc[mt][nt];
            if (outmode == 0) {
                *(float2*)(C + (size_t)row * 1024 + col0)       = make_float2(d[0], d[1]);
                *(float2*)(C + (size_t)(row + 8) * 1024 + col0) = make_float2(d[2], d[3]);
            } else {
                const int h = col0 >> 6, dd = col0 & 63;
                int b = row >> 11, t = row & 2047;
                *(float2*)(C + (((size_t)(b * H_ + h) * T_ + t) * DH + dd)) = make_float2(d[0], d[1]);
                b = (row + 8) >> 11; t = (row + 8) & 2047;
                *(float2*)(C + (((size_t)(b * H_ + h) * T_ + t) * DH + dd)) = make_float2(d[2], d[3]);
            }
        }
    }
}

// ---------------------------------------------------------------------------
// Tensor-core flash attention. Br=Bc=64, 4 warps (16 q-rows each), Dh=64.
// QK^T and PV on m16n8k16 bf16 3-term split; online softmax in fragments.
// K smem: [key][dhalf] packed; V smem: transposed [dh][keyhalf]; stride 36.
// ---------------------------------------------------------------------------
#define STR 36
__global__ __launch_bounds__(128) void flash_attn_mma(
    const float* __restrict__ Q, const float* __restrict__ K,
    const float* __restrict__ V, const unsigned char* __restrict__ mask,
    float* __restrict__ O)
{
    __shared__ uint32_t Kh[64*STR], Kl[64*STR], Vh[64*STR], Vl[64*STR];

    const int tid = threadIdx.x;
    const int w = tid >> 5, lane = tid & 31;
    const int lr = lane >> 2, lc = lane & 3;
    const int bh = blockIdx.y, b = bh >> 4, h = bh & 15;
    const int q0 = blockIdx.x * 64;

    // Q fragments (scaled by 1/sqrt(64)), split into hi/lo
    uint32_t qh[4][4], ql[4][4];
    {
        const float* Qb = Q + ((size_t)bh * 2048 + q0 + w * 16) * 64;
#pragma unroll
        for (int c = 0; c < 4; c++) {
#pragma unroll
            for (int rr = 0; rr < 2; rr++) {
                const float* p0 = Qb + (lr + rr * 8) * 64 + c * 16 + lc * 2;
                float2 x = *(const float2*)p0;
                float2 y = *(const float2*)(p0 + 8);
                x.x *= 0.125f; x.y *= 0.125f; y.x *= 0.125f; y.y *= 0.125f;
                split2(x.x, x.y, qh[c][rr],     ql[c][rr]);
                split2(y.x, y.y, qh[c][2 + rr], ql[c][2 + rr]);
            }
        }
    }

    float m0 = -1e30f, m1 = -1e30f, l0 = 0.f, l1 = 0.f;
    float o[8][4];
#pragma unroll
    for (int nt = 0; nt < 8; nt++)
#pragma unroll
        for (int i = 0; i < 4; i++) o[nt][i] = 0.f;

    const unsigned char* mrow0 = mask + ((size_t)b * 2048 + q0 + w * 16 + lr) * 2048;
    const unsigned char* mrow1 = mrow0 + 8 * 2048;

    for (int kt = 0; kt < 2048; kt += 64) {
        __syncthreads();
        {   // K tile: packed along dh
            const int dhalf = tid & 31, key0 = tid >> 5;
            const float* Kb = K + ((size_t)bh * 2048 + kt) * 64;
#pragma unroll
            for (int i = 0; i < 16; i++) {
                int key = key0 + i * 4;
                float2 x = *(const float2*)(Kb + key * 64 + dhalf * 2);
                uint32_t hh, ll; split2(x.x, x.y, hh, ll);
                Kh[key * STR + dhalf] = hh; Kl[key * STR + dhalf] = ll;
            }
            // V tile transposed: [d][keypair]
            const int d = tid & 63, kp0 = tid >> 6;
            const float* Vb = V + ((size_t)bh * 2048 + kt) * 64;
#pragma unroll
            for (int i = 0; i < 16; i++) {
                int kp = kp0 + i * 2;
                float v0 = Vb[(2 * kp) * 64 + d];
                float v1 = Vb[(2 * kp + 1) * 64 + d];
                uint32_t hh, ll; split2(v0, v1, hh, ll);
                Vh[d * STR + kp] = hh; Vl[d * STR + kp] = ll;
            }
        }
        __syncthreads();

        // S = Q K^T  (warp computes 16x64)
        float s[8][4];
#pragma unroll
        for (int nt = 0; nt < 8; nt++)
#pragma unroll
            for (int i = 0; i < 4; i++) s[nt][i] = 0.f;
#pragma unroll
        for (int c = 0; c < 4; c++) {
#pragma unroll
            for (int nt = 0; nt < 8; nt++) {
                const int cc = nt * 8 + lr;
                const int k0 = c * 8 + lc;
                uint32_t bh0 = Kh[cc * STR + k0];
                uint32_t bh1 = Kh[cc * STR + k0 + 4];
                uint32_t bl0 = Kl[cc * STR + k0];
                uint32_t bl1 = Kl[cc * STR + k0 + 4];
                mma_bf16(s[nt], qh[c], bh0, bh1);
                mma_bf16(s[nt], qh[c], bl0, bl1);
                mma_bf16(s[nt], ql[c], bh0, bh1);
            }
        }

        // mask
#pragma unroll
        for (int nt = 0; nt < 8; nt++) {
            const int cc = kt + nt * 8 + lc * 2;
            if (mrow0[cc])     s[nt][0] = -1e30f;
            if (mrow0[cc + 1]) s[nt][1] = -1e30f;
            if (mrow1[cc])     s[nt][2] = -1e30f;
            if (mrow1[cc + 1]) s[nt][3] = -1e30f;
        }

        // online softmax
        float tm0 = -1e30f, tm1 = -1e30f;
#pragma unroll
        for (int nt = 0; nt < 8; nt++) {
            tm0 = fmaxf(tm0, fmaxf(s[nt][0], s[nt][1]));
            tm1 = fmaxf(tm1, fmaxf(s[nt][2], s[nt][3]));
        }
        tm0 = fmaxf(tm0, __shfl_xor_sync(0xffffffff, tm0, 1));
        tm0 = fmaxf(tm0, __shfl_xor_sync(0xffffffff, tm0, 2));
        tm1 = fmaxf(tm1, __shfl_xor_sync(0xffffffff, tm1, 1));
        tm1 = fmaxf(tm1, __shfl_xor_sync(0xffffffff, tm1, 2));
        float mn0 = fmaxf(m0, tm0), mn1 = fmaxf(m1, tm1);
        float cr0 = __expf(m0 - mn0), cr1 = __expf(m1 - mn1);
        m0 = mn0; m1 = mn1;
        float ts0 = 0.f, ts1 = 0.f;
#pragma unroll
        for (int nt = 0; nt < 8; nt++) {
            s[nt][0] = __expf(s[nt][0] - mn0);
            s[nt][1] = __expf(s[nt][1] - mn0);
            s[nt][2] = __expf(s[nt][2] - mn1);
            s[nt][3] = __expf(s[nt][3] - mn1);
            ts0 += s[nt][0] + s[nt][1];
            ts1 += s[nt][2] + s[nt][3];
        }
        ts0 += __shfl_xor_sync(0xffffffff, ts0, 1);
        ts0 += __shfl_xor_sync(0xffffffff, ts0, 2);
        ts1 += __shfl_xor_sync(0xffffffff, ts1, 1);
        ts1 += __shfl_xor_sync(0xffffffff, ts1, 2);
        l0 = l0 * cr0 + ts0;
        l1 = l1 * cr1 + ts1;
#pragma unroll
        for (int nt = 0; nt < 8; nt++) {
            o[nt][0] *= cr0; o[nt][1] *= cr0;
            o[nt][2] *= cr1; o[nt][3] *= cr1;
        }

        // PV: A = P (fragments in-register from accumulator layout), B = V^T
#pragma unroll
        for (int kc = 0; kc < 4; kc++) {
            uint32_t ph[4], pl[4];
            split2(s[2*kc][0],   s[2*kc][1],   ph[0], pl[0]);
            split2(s[2*kc][2],   s[2*kc][3],   ph[1], pl[1]);
            split2(s[2*kc+1][0], s[2*kc+1][1], ph[2], pl[2]);
            split2(s[2*kc+1][2], s[2*kc+1][3], ph[3], pl[3]);
#pragma unroll
            for (int nt = 0; nt < 8; nt++) {
                const int n = nt * 8 + lr;
                const int k0 = kc * 8 + lc;
                uint32_t bh0 = Vh[n * STR + k0];
                uint32_t bh1 = Vh[n * STR + k0 + 4];
                uint32_t bl0 = Vl[n * STR + k0];
                uint32_t bl1 = Vl[n * STR + k0 + 4];
                mma_bf16(o[nt], ph, bh0, bh1);
                mma_bf16(o[nt], ph, bl0, bl1);
                mma_bf16(o[nt], pl, bh0, bh1);
            }
        }
    }

    const float inv0 = 1.f / l0, inv1 = 1.f / l1;
    const int t = q0 + w * 16 + lr;
    float* Ob = O + ((size_t)b * 2048 + t) * 1024 + h * 64;
#pragma unroll
    for (int nt = 0; nt < 8; nt++) {
        const int col = nt * 8 + lc * 2;
        *(float2*)(Ob + col)            = make_float2(o[nt][0] * inv0, o[nt][1] * inv0);
        *(float2*)(Ob + 8 * 1024 + col) = make_float2(o[nt][2] * inv1, o[nt][3] * inv1);
    }
}

extern "C" void kernel_launch(void* const* d_in, const int* in_sizes, int n_in,
                              void* d_out, int out_size)
{
    const float* query = (const float*)d_in[0];
    const float* key   = (const float*)d_in[1];
    const float* value = (const float*)d_in[2];
    const unsigned char* mask = (const unsigned char*)d_in[3];
    const float* Wq = (const float*)d_in[4];
    const float* Wk = (const float*)d_in[5];
    const float* Wv = (const float*)d_in[6];
    const float* Wo = (const float*)d_in[7];

    void *pQ, *pK, *pV, *pA;
    cudaGetSymbolAddress(&pQ, g_Q);
    cudaGetSymbolAddress(&pK, g_K);
    cudaGetSymbolAddress(&pV, g_V);
    cudaGetSymbolAddress(&pA, g_attn);

    dim3 gg(1024 / 128, 4096 / 128);   // (8, 32)
    bf16_gemm<<<gg, 256>>>(query, Wq, (float*)pQ, 1);
    bf16_gemm<<<gg, 256>>>(key,   Wk, (float*)pK, 1);
    bf16_gemm<<<gg, 256>>>(value, Wv, (float*)pV, 1);

    dim3 ga(T_ / 64, B_ * H_);         // (32, 32)
    flash_attn_mma<<<ga, 128>>>((const float*)pQ, (const float*)pK, (const float*)pV,
                                mask, (float*)pA);

    bf16_gemm<<<gg, 256>>>((const float*)pA, Wo, (float*)d_out, 0);
}

// round 5
// speedup vs baseline: 3.1731x; 1.0739x over previous
#include <cuda_runtime.h>
#include <cstdint>
#include <math.h>

#define B_  2
#define T_  2048
#define D_  1024
#define H_  16
#define DH  64

// Scratch (allocation-free contract: __device__ globals)
__device__ uint32_t g_Qh[B_*H_*T_*32];
__device__ uint32_t g_Ql[B_*H_*T_*32];
__device__ uint32_t g_Kh[B_*H_*T_*32];
__device__ uint32_t g_Kl[B_*H_*T_*32];
__device__ float    g_V [B_*H_*T_*DH];
__device__ float    g_attn[(size_t)B_*T_*D_];

// ---------------------------------------------------------------------------
// bf16 split helpers: x = hi + lo captures ~17 mantissa bits.
// packbf: x -> low 16 bits, y -> high 16 bits (mma element order: low = even k)
// ---------------------------------------------------------------------------
__device__ __forceinline__ uint32_t packbf(float x, float y) {
    uint32_t r; asm("cvt.rn.bf16x2.f32 %0, %1, %2;" : "=r"(r) : "f"(y), "f"(x)); return r;
}
__device__ __forceinline__ void split2(float x, float y, uint32_t& h, uint32_t& l) {
    h = packbf(x, y);
    float hx = __uint_as_float(h << 16);
    float hy = __uint_as_float(h & 0xFFFF0000u);
    l = packbf(x - hx, y - hy);
}
__device__ __forceinline__ void mma_bf16(float* d, const uint32_t* a, uint32_t b0, uint32_t b1) {
    asm volatile("mma.sync.aligned.m16n8k16.row.col.f32.bf16.bf16.f32 "
        "{%0,%1,%2,%3}, {%4,%5,%6,%7}, {%8,%9}, {%0,%1,%2,%3};"
        : "+f"(d[0]), "+f"(d[1]), "+f"(d[2]), "+f"(d[3])
        : "r"(a[0]), "r"(a[1]), "r"(a[2]), "r"(a[3]), "r"(b0), "r"(b1));
}

// ---------------------------------------------------------------------------
// Shared GEMM mainloop: C = A(128 rows of MxK) @ W^T(128 rows of NxK), K=1024.
// Double-buffered smem (uint2 = (hi,lo) bf16x2 pairs), K_tile=32.
// 8 warps, warp tile 64x32, m16n8k16, 3-term split.
// ---------------------------------------------------------------------------
#define GS2 20           // uint2 per smem row (16 khalf + 4 pad)
#define STAGE_U2 (128*GS2)

__device__ __forceinline__ void gemm_mainloop(
    const float* __restrict__ A, const float* __restrict__ W,
    int bm, int bn, uint2* Sa, uint2* Sb, float acc[4][4][4],
    int wm, int wn, int lr, int lc, int tid)
{
    const int kh = tid & 15, row0 = tid >> 4;
    float2 aR[8], bR[8];

#pragma unroll
    for (int p = 0; p < 8; ++p) {
        int row = row0 + p * 16;
        aR[p] = *(const float2*)(A + (size_t)(bm + row) * 1024 + 2 * kh);
        bR[p] = *(const float2*)(W + (size_t)(bn + row) * 1024 + 2 * kh);
    }
#pragma unroll
    for (int p = 0; p < 8; ++p) {
        int row = row0 + p * 16;
        uint32_t h, l;
        split2(aR[p].x, aR[p].y, h, l); Sa[row * GS2 + kh] = make_uint2(h, l);
        split2(bR[p].x, bR[p].y, h, l); Sb[row * GS2 + kh] = make_uint2(h, l);
    }
    __syncthreads();

    for (int it = 0; it < 32; ++it) {
        if (it < 31) {
            const int kt = (it + 1) * 32;
#pragma unroll
            for (int p = 0; p < 8; ++p) {
                int row = row0 + p * 16;
                aR[p] = *(const float2*)(A + (size_t)(bm + row) * 1024 + kt + 2 * kh);
                bR[p] = *(const float2*)(W + (size_t)(bn + row) * 1024 + kt + 2 * kh);
            }
        }
        const uint2* sa = Sa + (it & 1) * STAGE_U2;
        const uint2* sb = Sb + (it & 1) * STAGE_U2;
#pragma unroll
        for (int c = 0; c < 2; ++c) {
            uint32_t ah[4][4], al[4][4];
#pragma unroll
            for (int mt = 0; mt < 4; ++mt) {
                const int r0 = wm + mt * 16 + lr;
                const int k0 = c * 8 + lc;
                uint2 u0 = sa[r0 * GS2 + k0];
                uint2 u1 = sa[(r0 + 8) * GS2 + k0];
                uint2 u2 = sa[r0 * GS2 + k0 + 4];
                uint2 u3 = sa[(r0 + 8) * GS2 + k0 + 4];
                ah[mt][0] = u0.x; ah[mt][1] = u1.x; ah[mt][2] = u2.x; ah[mt][3] = u3.x;
                al[mt][0] = u0.y; al[mt][1] = u1.y; al[mt][2] = u2.y; al[mt][3] = u3.y;
            }
#pragma unroll
            for (int nt = 0; nt < 4; ++nt) {
                const int cc = wn + nt * 8 + lr;
                const int k0 = c * 8 + lc;
                uint2 v0 = sb[cc * GS2 + k0];
                uint2 v1 = sb[cc * GS2 + k0 + 4];
#pragma unroll
                for (int mt = 0; mt < 4; ++mt) {
                    mma_bf16(acc[mt][nt], ah[mt], v0.x, v1.x);
                    mma_bf16(acc[mt][nt], ah[mt], v0.y, v1.y);
                    mma_bf16(acc[mt][nt], al[mt], v0.x, v1.x);
                }
            }
        }
        if (it < 31) {
            uint2* da = Sa + ((it + 1) & 1) * STAGE_U2;
            uint2* db = Sb + ((it + 1) & 1) * STAGE_U2;
#pragma unroll
            for (int p = 0; p < 8; ++p) {
                int row = row0 + p * 16;
                uint32_t h, l;
                split2(aR[p].x, aR[p].y, h, l); da[row * GS2 + kh] = make_uint2(h, l);
                split2(bR[p].x, bR[p].y, h, l); db[row * GS2 + kh] = make_uint2(h, l);
            }
        }
        __syncthreads();
    }
}

// ---------------------------------------------------------------------------
// Fused QKV projection. grid (24, 32): which = bx/8. Q,K -> packed bf16 hi/lo
// (Q pre-scaled by 1/8); V -> float per-head layout.
// ---------------------------------------------------------------------------
__global__ __launch_bounds__(256) void gemm_qkv(
    const float* __restrict__ q, const float* __restrict__ k, const float* __restrict__ v,
    const float* __restrict__ Wq, const float* __restrict__ Wk, const float* __restrict__ Wv,
    uint32_t* __restrict__ Qh, uint32_t* __restrict__ Ql,
    uint32_t* __restrict__ Kh, uint32_t* __restrict__ Kl,
    float* __restrict__ Vf)
{
    extern __shared__ __align__(16) uint2 smemu[];
    uint2* Sa = smemu;
    uint2* Sb = smemu + 2 * STAGE_U2;

    const int which = blockIdx.x >> 3;
    const int bn = (blockIdx.x & 7) * 128;
    const int bm = blockIdx.y * 128;
    const float* A = which == 0 ? q : which == 1 ? k : v;
    const float* W = which == 0 ? Wq : which == 1 ? Wk : Wv;

    const int tid = threadIdx.x;
    const int wid = tid >> 5, lane = tid & 31;
    const int wm = (wid & 1) * 64, wn = (wid >> 1) * 32;
    const int lr = lane >> 2, lc = lane & 3;

    float acc[4][4][4];
#pragma unroll
    for (int mt = 0; mt < 4; mt++)
#pragma unroll
        for (int nt = 0; nt < 4; nt++)
#pragma unroll
            for (int i = 0; i < 4; i++) acc[mt][nt][i] = 0.f;

    gemm_mainloop(A, W, bm, bn, Sa, Sb, acc, wm, wn, lr, lc, tid);

    if (which < 2) {
        uint32_t* Ph = which == 0 ? Qh : Kh;
        uint32_t* Pl = which == 0 ? Ql : Kl;
        const float sc = which == 0 ? 0.125f : 1.0f;
#pragma unroll
        for (int mt = 0; mt < 4; ++mt)
#pragma unroll
            for (int nt = 0; nt < 4; ++nt) {
                const int row  = bm + wm + mt * 16 + lr;
                const int col0 = bn + wn + nt * 8 + lc * 2;
                const int hh = col0 >> 6, j = (col0 & 63) >> 1;
                const float* d = acc[mt][nt];
                uint32_t h, l;
                int b = row >> 11, t = row & 2047;
                size_t base = ((size_t)(b * 16 + hh) * 2048 + t) * 32 + j;
                split2(d[0] * sc, d[1] * sc, h, l);
                Ph[base] = h; Pl[base] = l;
                b = (row + 8) >> 11; t = (row + 8) & 2047;
                base = ((size_t)(b * 16 + hh) * 2048 + t) * 32 + j;
                split2(d[2] * sc, d[3] * sc, h, l);
                Ph[base] = h; Pl[base] = l;
            }
    } else {
#pragma unroll
        for (int mt = 0; mt < 4; ++mt)
#pragma unroll
            for (int nt = 0; nt < 4; ++nt) {
                const int row  = bm + wm + mt * 16 + lr;
                const int col0 = bn + wn + nt * 8 + lc * 2;
                const int hh = col0 >> 6, dd = col0 & 63;
                const float* d = acc[mt][nt];
                int b = row >> 11, t = row & 2047;
                *(float2*)(Vf + (((size_t)(b * 16 + hh) * 2048 + t) * 64 + dd)) = make_float2(d[0], d[1]);
                b = (row + 8) >> 11; t = (row + 8) & 2047;
                *(float2*)(Vf + (((size_t)(b * 16 + hh) * 2048 + t) * 64 + dd)) = make_float2(d[2], d[3]);
            }
    }
}

// ---------------------------------------------------------------------------
// Output projection: C = A @ Wo^T, row-major out. grid (8, 32).
// ---------------------------------------------------------------------------
__global__ __launch_bounds__(256) void gemm_oproj(
    const float* __restrict__ A, const float* __restrict__ W, float* __restrict__ C)
{
    extern __shared__ __align__(16) uint2 smemu[];
    uint2* Sa = smemu;
    uint2* Sb = smemu + 2 * STAGE_U2;

    const int bn = blockIdx.x * 128;
    const int bm = blockIdx.y * 128;
    const int tid = threadIdx.x;
    const int wid = tid >> 5, lane = tid & 31;
    const int wm = (wid & 1) * 64, wn = (wid >> 1) * 32;
    const int lr = lane >> 2, lc = lane & 3;

    float acc[4][4][4];
#pragma unroll
    for (int mt = 0; mt < 4; mt++)
#pragma unroll
        for (int nt = 0; nt < 4; nt++)
#pragma unroll
            for (int i = 0; i < 4; i++) acc[mt][nt][i] = 0.f;

    gemm_mainloop(A, W, bm, bn, Sa, Sb, acc, wm, wn, lr, lc, tid);

#pragma unroll
    for (int mt = 0; mt < 4; ++mt)
#pragma unroll
        for (int nt = 0; nt < 4; ++nt) {
            const int row  = bm + wm + mt * 16 + lr;
            const int col0 = bn + wn + nt * 8 + lc * 2;
            const float* d = acc[mt][nt];
            *(float2*)(C + (size_t)row * 1024 + col0)       = make_float2(d[0], d[1]);
            *(float2*)(C + (size_t)(row + 8) * 1024 + col0) = make_float2(d[2], d[3]);
        }
}

// ---------------------------------------------------------------------------
// Flash attention v2: Q/K pre-split packed globals, uint2 smem, LDS.64 frags.
// Br=64 (4 warps x 16 q-rows), Bc=64. 128 threads, target 4 CTAs/SM.
// ---------------------------------------------------------------------------
#define KS2 36   // uint2 stride for K/V smem rows
__global__ __launch_bounds__(128, 4) void flash_attn2(
    const uint32_t* __restrict__ Qh, const uint32_t* __restrict__ Ql,
    const uint32_t* __restrict__ Kh, const uint32_t* __restrict__ Kl,
    const float* __restrict__ V, const unsigned char* __restrict__ mask,
    float* __restrict__ O)
{
    __shared__ __align__(16) uint2 SK[64 * KS2];
    __shared__ __align__(16) uint2 SV[64 * KS2];

    const int tid = threadIdx.x;
    const int w = tid >> 5, lane = tid & 31;
    const int lr = lane >> 2, lc = lane & 3;
    const int bh = blockIdx.y, b = bh >> 4, h = bh & 15;
    const int q0 = blockIdx.x * 64;
    const int t0 = q0 + w * 16;

    // Q fragments: direct packed loads (already scaled by 1/8)
    uint32_t qh[4][4], ql[4][4];
    {
        const size_t base0 = ((size_t)bh * 2048 + t0 + lr) * 32;
        const size_t base1 = base0 + 8 * 32;
#pragma unroll
        for (int c = 0; c < 4; c++) {
            const int j = c * 8 + lc;
            qh[c][0] = Qh[base0 + j];     ql[c][0] = Ql[base0 + j];
            qh[c][1] = Qh[base1 + j];     ql[c][1] = Ql[base1 + j];
            qh[c][2] = Qh[base0 + j + 4]; ql[c][2] = Ql[base0 + j + 4];
            qh[c][3] = Qh[base1 + j + 4]; ql[c][3] = Ql[base1 + j + 4];
        }
    }

    float m0 = -1e30f, m1 = -1e30f, l0 = 0.f, l1 = 0.f;
    float o[8][4];
#pragma unroll
    for (int nt = 0; nt < 8; nt++)
#pragma unroll
        for (int i = 0; i < 4; i++) o[nt][i] = 0.f;

    const unsigned char* mrow0 = mask + ((size_t)b * 2048 + t0 + lr) * 2048;
    const unsigned char* mrow1 = mrow0 + 8 * 2048;

    const int vd  = tid & 63;        // V producer: d index
    const int vk0 = tid >> 6;        // 0..1

    for (int kt = 0; kt < 2048; kt += 64) {
        __syncthreads();
        {   // K tile: pure copy of packed words
            const uint32_t* KhB = Kh + ((size_t)bh * 2048 + kt) * 32;
            const uint32_t* KlB = Kl + ((size_t)bh * 2048 + kt) * 32;
#pragma unroll
            for (int i = 0; i < 16; i++) {
                int idx = tid + i * 128;
                int key = idx >> 5, j = idx & 31;
                SK[key * KS2 + j] = make_uint2(KhB[key * 32 + j], KlB[key * 32 + j]);
            }
            // V tile: transpose + split, XOR-swizzled keypair index
            const float* Vb = V + ((size_t)bh * 2048 + kt) * 64;
            const int sw = (vd >> 2) & 3;
#pragma unroll
            for (int i = 0; i < 16; i++) {
                int kp = vk0 + i * 2;
                float v0 = Vb[(2 * kp) * 64 + vd];
                float v1 = Vb[(2 * kp + 1) * 64 + vd];
                uint32_t hh, ll; split2(v0, v1, hh, ll);
                SV[vd * KS2 + (kp ^ sw)] = make_uint2(hh, ll);
            }
        }
        __syncthreads();

        // S = Q K^T
        float s[8][4];
#pragma unroll
        for (int nt = 0; nt < 8; nt++)
#pragma unroll
            for (int i = 0; i < 4; i++) s[nt][i] = 0.f;
#pragma unroll
        for (int c = 0; c < 4; c++) {
#pragma unroll
            for (int nt = 0; nt < 8; nt++) {
                const int cc = nt * 8 + lr;
                const int k0 = c * 8 + lc;
                uint2 u0 = SK[cc * KS2 + k0];
                uint2 u1 = SK[cc * KS2 + k0 + 4];
                mma_bf16(s[nt], qh[c], u0.x, u1.x);
                mma_bf16(s[nt], qh[c], u0.y, u1.y);
                mma_bf16(s[nt], ql[c], u0.x, u1.x);
            }
        }

        // mask
#pragma unroll
        for (int nt = 0; nt < 8; nt++) {
            const int cc = kt + nt * 8 + lc * 2;
            if (mrow0[cc])     s[nt][0] = -1e30f;
            if (mrow0[cc + 1]) s[nt][1] = -1e30f;
            if (mrow1[cc])     s[nt][2] = -1e30f;
            if (mrow1[cc + 1]) s[nt][3] = -1e30f;
        }

        // online softmax
        float tm0 = -1e30f, tm1 = -1e30f;
#pragma unroll
        for (int nt = 0; nt < 8; nt++) {
            tm0 = fmaxf(tm0, fmaxf(s[nt][0], s[nt][1]));
            tm1 = fmaxf(tm1, fmaxf(s[nt][2], s[nt][3]));
        }
        tm0 = fmaxf(tm0, __shfl_xor_sync(0xffffffff, tm0, 1));
        tm0 = fmaxf(tm0, __shfl_xor_sync(0xffffffff, tm0, 2));
        tm1 = fmaxf(tm1, __shfl_xor_sync(0xffffffff, tm1, 1));
        tm1 = fmaxf(tm1, __shfl_xor_sync(0xffffffff, tm1, 2));
        float mn0 = fmaxf(m0, tm0), mn1 = fmaxf(m1, tm1);
        float cr0 = __expf(m0 - mn0), cr1 = __expf(m1 - mn1);
        m0 = mn0; m1 = mn1;
        float ts0 = 0.f, ts1 = 0.f;
#pragma unroll
        for (int nt = 0; nt < 8; nt++) {
            s[nt][0] = __expf(s[nt][0] - mn0);
            s[nt][1] = __expf(s[nt][1] - mn0);
            s[nt][2] = __expf(s[nt][2] - mn1);
            s[nt][3] = __expf(s[nt][3] - mn1);
            ts0 += s[nt][0] + s[nt][1];
            ts1 += s[nt][2] + s[nt][3];
        }
        ts0 += __shfl_xor_sync(0xffffffff, ts0, 1);
        ts0 += __shfl_xor_sync(0xffffffff, ts0, 2);
        ts1 += __shfl_xor_sync(0xffffffff, ts1, 1);
        ts1 += __shfl_xor_sync(0xffffffff, ts1, 2);
        l0 = l0 * cr0 + ts0;
        l1 = l1 * cr1 + ts1;
#pragma unroll
        for (int nt = 0; nt < 8; nt++) {
            o[nt][0] *= cr0; o[nt][1] *= cr0;
            o[nt][2] *= cr1; o[nt][3] *= cr1;
        }

        // PV
#pragma unroll
        for (int kc = 0; kc < 4; kc++) {
            uint32_t ph[4], pl[4];
            split2(s[2*kc][0],   s[2*kc][1],   ph[0], pl[0]);
            split2(s[2*kc][2],   s[2*kc][3],   ph[1], pl[1]);
            split2(s[2*kc+1][0], s[2*kc+1][1], ph[2], pl[2]);
            split2(s[2*kc+1][2], s[2*kc+1][3], ph[3], pl[3]);
#pragma unroll
            for (int nt = 0; nt < 8; nt++) {
                const int n = nt * 8 + lr;
                const int x = (n >> 2) & 3;
                const int j0 = kc * 8 + lc;
                uint2 u0 = SV[n * KS2 + (j0 ^ x)];
                uint2 u1 = SV[n * KS2 + ((j0 + 4) ^ x)];
                mma_bf16(o[nt], ph, u0.x, u1.x);
                mma_bf16(o[nt], ph, u0.y, u1.y);
                mma_bf16(o[nt], pl, u0.x, u1.x);
            }
        }
    }

    const float inv0 = 1.f / l0, inv1 = 1.f / l1;
    float* Ob = O + ((size_t)b * 2048 + t0 + lr) * 1024 + h * 64;
#pragma unroll
    for (int nt = 0; nt < 8; nt++) {
        const int col = nt * 8 + lc * 2;
        *(float2*)(Ob + col)            = make_float2(o[nt][0] * inv0, o[nt][1] * inv0);
        *(float2*)(Ob + 8 * 1024 + col) = make_float2(o[nt][2] * inv1, o[nt][3] * inv1);
    }
}

extern "C" void kernel_launch(void* const* d_in, const int* in_sizes, int n_in,
                              void* d_out, int out_size)
{
    const float* query = (const float*)d_in[0];
    const float* key   = (const float*)d_in[1];
    const float* value = (const float*)d_in[2];
    const unsigned char* mask = (const unsigned char*)d_in[3];
    const float* Wq = (const float*)d_in[4];
    const float* Wk = (const float*)d_in[5];
    const float* Wv = (const float*)d_in[6];
    const float* Wo = (const float*)d_in[7];

    void *pQh, *pQl, *pKh, *pKl, *pV, *pA;
    cudaGetSymbolAddress(&pQh, g_Qh);
    cudaGetSymbolAddress(&pQl, g_Ql);
    cudaGetSymbolAddress(&pKh, g_Kh);
    cudaGetSymbolAddress(&pKl, g_Kl);
    cudaGetSymbolAddress(&pV,  g_V);
    cudaGetSymbolAddress(&pA,  g_attn);

    const int SMEM_GEMM = 4 * STAGE_U2 * 8;   // 81920 B
    cudaFuncSetAttribute(gemm_qkv,  cudaFuncAttributeMaxDynamicSharedMemorySize, SMEM_GEMM);
    cudaFuncSetAttribute(gemm_oproj, cudaFuncAttributeMaxDynamicSharedMemorySize, SMEM_GEMM);

    dim3 gq(24, 32);
    gemm_qkv<<<gq, 256, SMEM_GEMM>>>(query, key, value, Wq, Wk, Wv,
        (uint32_t*)pQh, (uint32_t*)pQl, (uint32_t*)pKh, (uint32_t*)pKl, (float*)pV);

    dim3 ga(T_ / 64, B_ * H_);        // (32, 32)
    flash_attn2<<<ga, 128>>>((const uint32_t*)pQh, (const uint32_t*)pQl,
                             (const uint32_t*)pKh, (const uint32_t*)pKl,
                             (const float*)pV, mask, (float*)pA);

    dim3 go(8, 32);
    gemm_oproj<<<go, 256, SMEM_GEMM>>>((const float*)pA, Wo, (float*)d_out);
}

// round 6
// speedup vs baseline: 3.3030x; 1.0409x over previous
#include <cuda_runtime.h>
#include <cstdint>
#include <math.h>

#define B_  2
#define T_  2048
#define D_  1024
#define H_  16
#define DH  64

// ------------------------- scratch (__device__ globals) -------------------------
__device__ uint2 g_Qpk[B_*H_*T_*32];          // packed Q (scaled 1/8), [bh][t][j]
__device__ uint2 g_Kpk[B_*H_*T_*32];          // packed K
__device__ float g_V  [B_*H_*T_*DH];          // V float, per-head
__device__ uint2 g_Vpk[(size_t)B_*H_*DH*1024];// packed V^T, [bh][d][kp]
__device__ uint2 g_Apk[(size_t)B_*T_*512];    // packed attn output rows
__device__ uint2 g_qpk[(size_t)B_*T_*512];    // packed inputs
__device__ uint2 g_kpk[(size_t)B_*T_*512];
__device__ uint2 g_vpk[(size_t)B_*T_*512];
__device__ uint2 g_Wq[1024*512];
__device__ uint2 g_Wk[1024*512];
__device__ uint2 g_Wv[1024*512];
__device__ uint2 g_Wo[1024*512];

// ------------------------- helpers -------------------------
__device__ __forceinline__ uint32_t packbf(float x, float y) {
    uint32_t r; asm("cvt.rn.bf16x2.f32 %0, %1, %2;" : "=r"(r) : "f"(y), "f"(x)); return r;
}
__device__ __forceinline__ void split2(float x, float y, uint32_t& h, uint32_t& l) {
    h = packbf(x, y);
    float hx = __uint_as_float(h << 16);
    float hy = __uint_as_float(h & 0xFFFF0000u);
    l = packbf(x - hx, y - hy);
}
__device__ __forceinline__ void mma_bf16(float* d, const uint32_t* a, uint32_t b0, uint32_t b1) {
    asm volatile("mma.sync.aligned.m16n8k16.row.col.f32.bf16.bf16.f32 "
        "{%0,%1,%2,%3}, {%4,%5,%6,%7}, {%8,%9}, {%0,%1,%2,%3};"
        : "+f"(d[0]), "+f"(d[1]), "+f"(d[2]), "+f"(d[3])
        : "r"(a[0]), "r"(a[1]), "r"(a[2]), "r"(a[3]), "r"(b0), "r"(b1));
}
__device__ __forceinline__ uint32_t s2u(const void* p) {
    return (uint32_t)__cvta_generic_to_shared(p);
}
#define CP16(d, s) asm volatile("cp.async.cg.shared.global [%0], [%1], 16;" :: "r"(d), "l"(s))
#define CP_COMMIT  asm volatile("cp.async.commit_group;" ::: "memory")
#define CP_WAIT1   asm volatile("cp.async.wait_group 1;" ::: "memory")
#define CP_WAIT0   asm volatile("cp.async.wait_group 0;" ::: "memory")

// ------------------------- prep: pack float pairs -> (hi,lo) -------------------------
__global__ __launch_bounds__(256) void pack2(const float* __restrict__ X,
                                             uint2* __restrict__ P, int n2)
{
    for (int i = blockIdx.x * 256 + threadIdx.x; i < n2; i += gridDim.x * 256) {
        float2 v = ((const float2*)X)[i];
        uint32_t h, l; split2(v.x, v.y, h, l);
        P[i] = make_uint2(h, l);
    }
}

// ------------------------- prep: V float -> packed transposed -------------------------
__global__ __launch_bounds__(128) void v_pack(const float* __restrict__ V,
                                              uint2* __restrict__ Vpk)
{
    __shared__ float tile[64][65];
    const int tid = threadIdx.x;
    const int bh = blockIdx.y, kt = blockIdx.x * 64;
    const float* Vb = V + ((size_t)bh * 2048 + kt) * 64;
#pragma unroll
    for (int i = 0; i < 16; i++) {
        int idx = tid + i * 128;            // 2048 float2
        int r = idx >> 5, dp = idx & 31;
        float2 v = ((const float2*)Vb)[r * 32 + dp];
        tile[r][dp * 2] = v.x; tile[r][dp * 2 + 1] = v.y;
    }
    __syncthreads();
#pragma unroll
    for (int i = 0; i < 16; i++) {
        int idx = tid + i * 128;
        int d = idx >> 5, kp = idx & 31;
        uint32_t h, l; split2(tile[2 * kp][d], tile[2 * kp + 1][d], h, l);
        Vpk[((size_t)bh * 64 + d) * 1024 + (kt >> 1) + kp] = make_uint2(h, l);
    }
}

// ------------------------- GEMM mainloop (pre-packed inputs, cp.async) -------------------------
#define GS2 20
#define STAGE_U2 (128*GS2)

__device__ __forceinline__ void gemm_mainloop_pk(
    const uint2* __restrict__ Apk, const uint2* __restrict__ Wpk,
    int bm, int bn, uint2* Sa, uint2* Sb, float acc[4][4][4],
    int wm, int wn, int lr, int lc, int tid)
{
    const uint2* Abase = Apk + (size_t)bm * 512;
    const uint2* Bbase = Wpk + (size_t)bn * 512;

#define ISSUE(it_) do { \
    const int stage_ = (it_) & 1; \
    uint2* da_ = Sa + stage_ * STAGE_U2; \
    uint2* db_ = Sb + stage_ * STAGE_U2; \
    const uint2* As_ = Abase + (it_) * 16; \
    const uint2* Bs_ = Bbase + (it_) * 16; \
    _Pragma("unroll") \
    for (int t_ = 0; t_ < 4; t_++) { \
        int c_ = tid + t_ * 256; \
        int row_ = c_ >> 3, j_ = c_ & 7; \
        CP16(s2u(&da_[row_ * GS2 + 2 * j_]), &As_[(size_t)row_ * 512 + 2 * j_]); \
        CP16(s2u(&db_[row_ * GS2 + 2 * j_]), &Bs_[(size_t)row_ * 512 + 2 * j_]); \
    } \
} while(0)

    ISSUE(0); CP_COMMIT;
    for (int it = 0; it < 32; ++it) {
        if (it < 31) { ISSUE(it + 1); CP_COMMIT; CP_WAIT1; }
        else CP_WAIT0;
        __syncthreads();
        const uint2* sa = Sa + (it & 1) * STAGE_U2;
        const uint2* sb = Sb + (it & 1) * STAGE_U2;
#pragma unroll
        for (int c = 0; c < 2; ++c) {
            uint32_t ah[4][4], al[4][4];
#pragma unroll
            for (int mt = 0; mt < 4; ++mt) {
                const int r0 = wm + mt * 16 + lr;
                const int k0 = c * 8 + lc;
                uint2 u0 = sa[r0 * GS2 + k0];
                uint2 u1 = sa[(r0 + 8) * GS2 + k0];
                uint2 u2 = sa[r0 * GS2 + k0 + 4];
                uint2 u3 = sa[(r0 + 8) * GS2 + k0 + 4];
                ah[mt][0] = u0.x; ah[mt][1] = u1.x; ah[mt][2] = u2.x; ah[mt][3] = u3.x;
                al[mt][0] = u0.y; al[mt][1] = u1.y; al[mt][2] = u2.y; al[mt][3] = u3.y;
            }
#pragma unroll
            for (int nt = 0; nt < 4; ++nt) {
                const int cc = wn + nt * 8 + lr;
                const int k0 = c * 8 + lc;
                uint2 v0 = sb[cc * GS2 + k0];
                uint2 v1 = sb[cc * GS2 + k0 + 4];
#pragma unroll
                for (int mt = 0; mt < 4; ++mt) {
                    mma_bf16(acc[mt][nt], ah[mt], v0.x, v1.x);
                    mma_bf16(acc[mt][nt], ah[mt], v0.y, v1.y);
                    mma_bf16(acc[mt][nt], al[mt], v0.x, v1.x);
                }
            }
        }
        __syncthreads();
    }
#undef ISSUE
}

// ------------------------- fused QKV projection -------------------------
__global__ __launch_bounds__(256, 2) void gemm_qkv(
    const uint2* __restrict__ qpk, const uint2* __restrict__ kpk, const uint2* __restrict__ vpk,
    const uint2* __restrict__ Wq, const uint2* __restrict__ Wk, const uint2* __restrict__ Wv,
    uint2* __restrict__ Qpk, uint2* __restrict__ Kpk, float* __restrict__ Vf)
{
    extern __shared__ __align__(16) uint2 smemu[];
    uint2* Sa = smemu;
    uint2* Sb = smemu + 2 * STAGE_U2;

    const int which = blockIdx.x >> 3;
    const int bn = (blockIdx.x & 7) * 128;
    const int bm = blockIdx.y * 128;
    const uint2* A = which == 0 ? qpk : which == 1 ? kpk : vpk;
    const uint2* W = which == 0 ? Wq : which == 1 ? Wk : Wv;

    const int tid = threadIdx.x;
    const int wid = tid >> 5, lane = tid & 31;
    const int wm = (wid & 1) * 64, wn = (wid >> 1) * 32;
    const int lr = lane >> 2, lc = lane & 3;

    float acc[4][4][4];
#pragma unroll
    for (int mt = 0; mt < 4; mt++)
#pragma unroll
        for (int nt = 0; nt < 4; nt++)
#pragma unroll
            for (int i = 0; i < 4; i++) acc[mt][nt][i] = 0.f;

    gemm_mainloop_pk(A, W, bm, bn, Sa, Sb, acc, wm, wn, lr, lc, tid);

    if (which < 2) {
        uint2* P = which == 0 ? Qpk : Kpk;
        const float sc = which == 0 ? 0.125f : 1.0f;
#pragma unroll
        for (int mt = 0; mt < 4; ++mt)
#pragma unroll
            for (int nt = 0; nt < 4; ++nt) {
                const int row  = bm + wm + mt * 16 + lr;
                const int col0 = bn + wn + nt * 8 + lc * 2;
                const int hh = col0 >> 6, j = (col0 & 63) >> 1;
                const float* d = acc[mt][nt];
                uint32_t h, l;
                int b = row >> 11, t = row & 2047;
                split2(d[0] * sc, d[1] * sc, h, l);
                P[((size_t)(b * 16 + hh) * 2048 + t) * 32 + j] = make_uint2(h, l);
                b = (row + 8) >> 11; t = (row + 8) & 2047;
                split2(d[2] * sc, d[3] * sc, h, l);
                P[((size_t)(b * 16 + hh) * 2048 + t) * 32 + j] = make_uint2(h, l);
            }
    } else {
#pragma unroll
        for (int mt = 0; mt < 4; ++mt)
#pragma unroll
            for (int nt = 0; nt < 4; ++nt) {
                const int row  = bm + wm + mt * 16 + lr;
                const int col0 = bn + wn + nt * 8 + lc * 2;
                const int hh = col0 >> 6, dd = col0 & 63;
                const float* d = acc[mt][nt];
                int b = row >> 11, t = row & 2047;
                *(float2*)(Vf + (((size_t)(b * 16 + hh) * 2048 + t) * 64 + dd)) = make_float2(d[0], d[1]);
                b = (row + 8) >> 11; t = (row + 8) & 2047;
                *(float2*)(Vf + (((size_t)(b * 16 + hh) * 2048 + t) * 64 + dd)) = make_float2(d[2], d[3]);
            }
    }
}

// ------------------------- output projection -------------------------
__global__ __launch_bounds__(256, 2) void gemm_oproj(
    const uint2* __restrict__ Apk, const uint2* __restrict__ W, float* __restrict__ C)
{
    extern __shared__ __align__(16) uint2 smemu[];
    uint2* Sa = smemu;
    uint2* Sb = smemu + 2 * STAGE_U2;

    const int bn = blockIdx.x * 128;
    const int bm = blockIdx.y * 128;
    const int tid = threadIdx.x;
    const int wid = tid >> 5, lane = tid & 31;
    const int wm = (wid & 1) * 64, wn = (wid >> 1) * 32;
    const int lr = lane >> 2, lc = lane & 3;

    float acc[4][4][4];
#pragma unroll
    for (int mt = 0; mt < 4; mt++)
#pragma unroll
        for (int nt = 0; nt < 4; nt++)
#pragma unroll
            for (int i = 0; i < 4; i++) acc[mt][nt][i] = 0.f;

    gemm_mainloop_pk(Apk, W, bm, bn, Sa, Sb, acc, wm, wn, lr, lc, tid);

#pragma unroll
    for (int mt = 0; mt < 4; ++mt)
#pragma unroll
        for (int nt = 0; nt < 4; ++nt) {
            const int row  = bm + wm + mt * 16 + lr;
            const int col0 = bn + wn + nt * 8 + lc * 2;
            const float* d = acc[mt][nt];
            *(float2*)(C + (size_t)row * 1024 + col0)       = make_float2(d[0], d[1]);
            *(float2*)(C + (size_t)(row + 8) * 1024 + col0) = make_float2(d[2], d[3]);
        }
}

// ------------------------- flash attention -------------------------
#define KS2 36
__global__ __launch_bounds__(128, 4) void flash_attn3(
    const uint2* __restrict__ Qpk, const uint2* __restrict__ Kpk,
    const uint2* __restrict__ Vpk, const unsigned char* __restrict__ mask,
    uint2* __restrict__ Apk)
{
    __shared__ __align__(16) uint2 SK[64 * KS2];
    __shared__ __align__(16) uint2 SV[64 * KS2];

    const int tid = threadIdx.x;
    const int w = tid >> 5, lane = tid & 31;
    const int lr = lane >> 2, lc = lane & 3;
    const int bh = blockIdx.y, b = bh >> 4, h = bh & 15;
    const int q0 = blockIdx.x * 64;
    const int t0 = q0 + w * 16;

    uint32_t qh[4][4], ql[4][4];
    {
        const uint2* q0p = Qpk + ((size_t)bh * 2048 + t0 + lr) * 32;
        const uint2* q1p = q0p + 8 * 32;
#pragma unroll
        for (int c = 0; c < 4; c++) {
            const int j = c * 8 + lc;
            uint2 u;
            u = q0p[j];     qh[c][0] = u.x; ql[c][0] = u.y;
            u = q1p[j];     qh[c][1] = u.x; ql[c][1] = u.y;
            u = q0p[j + 4]; qh[c][2] = u.x; ql[c][2] = u.y;
            u = q1p[j + 4]; qh[c][3] = u.x; ql[c][3] = u.y;
        }
    }

    float m0 = -1e30f, m1 = -1e30f, l0 = 0.f, l1 = 0.f;
    float o[8][4];
#pragma unroll
    for (int nt = 0; nt < 8; nt++)
#pragma unroll
        for (int i = 0; i < 4; i++) o[nt][i] = 0.f;

    const unsigned char* mrow0 = mask + ((size_t)b * 2048 + t0 + lr) * 2048;
    const unsigned char* mrow1 = mrow0 + 8 * 2048;

    for (int kt = 0; kt < 2048; kt += 64) {
        __syncthreads();
        {   // producers: pure copies
            const uint2* KB = Kpk + ((size_t)bh * 2048 + kt) * 32;
            const uint2* VB = Vpk + (size_t)bh * 64 * 1024 + (kt >> 1);
#pragma unroll
            for (int i = 0; i < 16; i++) {
                int idx = tid + i * 128;
                int r = idx >> 5, j = idx & 31;
                SK[r * KS2 + j] = KB[r * 32 + j];
                SV[r * KS2 + (j ^ ((r >> 2) & 3))] = VB[(size_t)r * 1024 + j];
            }
        }
        __syncthreads();

        float s[8][4];
#pragma unroll
        for (int nt = 0; nt < 8; nt++)
#pragma unroll
            for (int i = 0; i < 4; i++) s[nt][i] = 0.f;
#pragma unroll
        for (int c = 0; c < 4; c++) {
#pragma unroll
            for (int nt = 0; nt < 8; nt++) {
                const int cc = nt * 8 + lr;
                const int k0 = c * 8 + lc;
                uint2 u0 = SK[cc * KS2 + k0];
                uint2 u1 = SK[cc * KS2 + k0 + 4];
                mma_bf16(s[nt], qh[c], u0.x, u1.x);
                mma_bf16(s[nt], qh[c], u0.y, u1.y);
                mma_bf16(s[nt], ql[c], u0.x, u1.x);
            }
        }

#pragma unroll
        for (int nt = 0; nt < 8; nt++) {
            const int cc = kt + nt * 8 + lc * 2;
            if (mrow0[cc])     s[nt][0] = -1e30f;
            if (mrow0[cc + 1]) s[nt][1] = -1e30f;
            if (mrow1[cc])     s[nt][2] = -1e30f;
            if (mrow1[cc + 1]) s[nt][3] = -1e30f;
        }

        float tm0 = -1e30f, tm1 = -1e30f;
#pragma unroll
        for (int nt = 0; nt < 8; nt++) {
            tm0 = fmaxf(tm0, fmaxf(s[nt][0], s[nt][1]));
            tm1 = fmaxf(tm1, fmaxf(s[nt][2], s[nt][3]));
        }
        tm0 = fmaxf(tm0, __shfl_xor_sync(0xffffffff, tm0, 1));
        tm0 = fmaxf(tm0, __shfl_xor_sync(0xffffffff, tm0, 2));
        tm1 = fmaxf(tm1, __shfl_xor_sync(0xffffffff, tm1, 1));
        tm1 = fmaxf(tm1, __shfl_xor_sync(0xffffffff, tm1, 2));
        float mn0 = fmaxf(m0, tm0), mn1 = fmaxf(m1, tm1);
        float cr0 = __expf(m0 - mn0), cr1 = __expf(m1 - mn1);
        m0 = mn0; m1 = mn1;
        float ts0 = 0.f, ts1 = 0.f;
#pragma unroll
        for (int nt = 0; nt < 8; nt++) {
            s[nt][0] = __expf(s[nt][0] - mn0);
            s[nt][1] = __expf(s[nt][1] - mn0);
            s[nt][2] = __expf(s[nt][2] - mn1);
            s[nt][3] = __expf(s[nt][3] - mn1);
            ts0 += s[nt][0] + s[nt][1];
            ts1 += s[nt][2] + s[nt][3];
        }
        ts0 += __shfl_xor_sync(0xffffffff, ts0, 1);
        ts0 += __shfl_xor_sync(0xffffffff, ts0, 2);
        ts1 += __shfl_xor_sync(0xffffffff, ts1, 1);
        ts1 += __shfl_xor_sync(0xffffffff, ts1, 2);
        l0 = l0 * cr0 + ts0;
        l1 = l1 * cr1 + ts1;
#pragma unroll
        for (int nt = 0; nt < 8; nt++) {
            o[nt][0] *= cr0; o[nt][1] *= cr0;
            o[nt][2] *= cr1; o[nt][3] *= cr1;
        }

#pragma unroll
        for (int kc = 0; kc < 4; kc++) {
            uint32_t ph[4], pl[4];
            split2(s[2*kc][0],   s[2*kc][1],   ph[0], pl[0]);
            split2(s[2*kc][2],   s[2*kc][3],   ph[1], pl[1]);
            split2(s[2*kc+1][0], s[2*kc+1][1], ph[2], pl[2]);
            split2(s[2*kc+1][2], s[2*kc+1][3], ph[3], pl[3]);
#pragma unroll
            for (int nt = 0; nt < 8; nt++) {
                const int n = nt * 8 + lr;
                const int x = (n >> 2) & 3;
                const int j0 = kc * 8 + lc;
                uint2 u0 = SV[n * KS2 + (j0 ^ x)];
                uint2 u1 = SV[n * KS2 + ((j0 + 4) ^ x)];
                mma_bf16(o[nt], ph, u0.x, u1.x);
                mma_bf16(o[nt], ph, u0.y, u1.y);
                mma_bf16(o[nt], pl, u0.x, u1.x);
            }
        }
    }

    const float inv0 = 1.f / l0, inv1 = 1.f / l1;
    uint2* A0 = Apk + ((size_t)b * 2048 + t0 + lr) * 512 + h * 32;
    uint2* A1 = A0 + 8 * 512;
#pragma unroll
    for (int nt = 0; nt < 8; nt++) {
        const int j = nt * 4 + lc;
        uint32_t hh, ll;
        split2(o[nt][0] * inv0, o[nt][1] * inv0, hh, ll);
        A0[j] = make_uint2(hh, ll);
        split2(o[nt][2] * inv1, o[nt][3] * inv1, hh, ll);
        A1[j] = make_uint2(hh, ll);
    }
}

extern "C" void kernel_launch(void* const* d_in, const int* in_sizes, int n_in,
                              void* d_out, int out_size)
{
    const float* query = (const float*)d_in[0];
    const float* key   = (const float*)d_in[1];
    const float* value = (const float*)d_in[2];
    const unsigned char* mask = (const unsigned char*)d_in[3];
    const float* Wq = (const float*)d_in[4];
    const float* Wk = (const float*)d_in[5];
    const float* Wv = (const float*)d_in[6];
    const float* Wo = (const float*)d_in[7];

    void *pQpk, *pKpk, *pV, *pVpk, *pApk, *pqpk, *pkpk, *pvpk, *pWq, *pWk, *pWv, *pWo;
    cudaGetSymbolAddress(&pQpk, g_Qpk);
    cudaGetSymbolAddress(&pKpk, g_Kpk);
    cudaGetSymbolAddress(&pV,   g_V);
    cudaGetSymbolAddress(&pVpk, g_Vpk);
    cudaGetSymbolAddress(&pApk, g_Apk);
    cudaGetSymbolAddress(&pqpk, g_qpk);
    cudaGetSymbolAddress(&pkpk, g_kpk);
    cudaGetSymbolAddress(&pvpk, g_vpk);
    cudaGetSymbolAddress(&pWq,  g_Wq);
    cudaGetSymbolAddress(&pWk,  g_Wk);
    cudaGetSymbolAddress(&pWv,  g_Wv);
    cudaGetSymbolAddress(&pWo,  g_Wo);

    const int SMEM_GEMM = 4 * STAGE_U2 * 8;   // 81920 B
    cudaFuncSetAttribute(gemm_qkv,   cudaFuncAttributeMaxDynamicSharedMemorySize, SMEM_GEMM);
    cudaFuncSetAttribute(gemm_oproj, cudaFuncAttributeMaxDynamicSharedMemorySize, SMEM_GEMM);

    // pack inputs + weights
    pack2<<<1024, 256>>>(query, (uint2*)pqpk, 4096 * 512);
    pack2<<<1024, 256>>>(key,   (uint2*)pkpk, 4096 * 512);
    pack2<<<1024, 256>>>(value, (uint2*)pvpk, 4096 * 512);
    pack2<<<512,  256>>>(Wq, (uint2*)pWq, 1024 * 512);
    pack2<<<512,  256>>>(Wk, (uint2*)pWk, 1024 * 512);
    pack2<<<512,  256>>>(Wv, (uint2*)pWv, 1024 * 512);
    pack2<<<512,  256>>>(Wo, (uint2*)pWo, 1024 * 512);

    dim3 gq(24, 32);
    gemm_qkv<<<gq, 256, SMEM_GEMM>>>((const uint2*)pqpk, (const uint2*)pkpk, (const uint2*)pvpk,
                                     (const uint2*)pWq, (const uint2*)pWk, (const uint2*)pWv,
                                     (uint2*)pQpk, (uint2*)pKpk, (float*)pV);

    dim3 gv(32, 32);
    v_pack<<<gv, 128>>>((const float*)pV, (uint2*)pVpk);

    dim3 ga(T_ / 64, B_ * H_);
    flash_attn3<<<ga, 128>>>((const uint2*)pQpk, (const uint2*)pKpk,
                             (const uint2*)pVpk, mask, (uint2*)pApk);

    dim3 go(8, 32);
    gemm_oproj<<<go, 256, SMEM_GEMM>>>((const uint2*)pApk, (const uint2*)pWo, (float*)d_out);
}